// round 5
// baseline (speedup 1.0000x reference)
#include <cuda_runtime.h>
#include <cstdint>

#define NB   64
#define NT   1024
#define NIN  256
#define NH   512
#define NTHR 256
#define CLU  8                    // cluster size = col-blocks per batch group
#define NGRP 16                   // batch groups (independent clusters)
#define NCTA (NGRP * CLU)

// ---------------- f32x2 packed helpers (sm_103a) -----------------------------
__device__ __forceinline__ uint64_t pk2(float x, float y) {
    uint64_t d; asm("mov.b64 %0, {%1, %2};" : "=l"(d) : "f"(x), "f"(y)); return d;
}
__device__ __forceinline__ uint64_t fma2(uint64_t a, uint64_t b, uint64_t c) {
    uint64_t d; asm("fma.rn.f32x2 %0, %1, %2, %3;" : "=l"(d) : "l"(a), "l"(b), "l"(c)); return d;
}
__device__ __forceinline__ uint64_t add2(uint64_t a, uint64_t b) {
    uint64_t d; asm("add.rn.f32x2 %0, %1, %2;" : "=l"(d) : "l"(a), "l"(b)); return d;
}
__device__ __forceinline__ uint32_t sm_u32(const void* p) {
    return (uint32_t)__cvta_generic_to_shared(p);
}

// cluster-scope mbarrier wait (acquire: orders peers' st.shared::cluster)
#define WAITC(addr, ph) do {                                                   \
    uint32_t _done;                                                            \
    do {                                                                       \
        asm volatile("{\n\t.reg .pred p;\n\t"                                  \
            "mbarrier.try_wait.parity.acquire.cluster.shared::cta.b64 p, [%1], %2, 0x989680;\n\t" \
            "selp.b32 %0, 1, 0, p;\n\t}"                                       \
            : "=r"(_done) : "r"(addr), "r"(ph) : "memory");                    \
    } while (!_done);                                                          \
} while (0)

#define ARRIVE_REMOTE(laddr, r) do {                                           \
    uint32_t _ra;                                                              \
    asm volatile("mapa.shared::cluster.u32 %0, %1, %2;"                        \
                 : "=r"(_ra) : "r"(laddr), "r"(r));                            \
    asm volatile("mbarrier.arrive.release.cluster.shared::cluster.b64 _, [%0];"\
                 :: "r"(_ra) : "memory");                                      \
} while (0)

// ---------------- Phase A: v_in = x @ W_in + b_in -> d_out -------------------
#define BM 64
#define BN 64
#define BK 16

__global__ __launch_bounds__(256) void gemm_vin(const float* __restrict__ A,
                                                const float* __restrict__ Bm,
                                                const float* __restrict__ bias,
                                                float* __restrict__ C) {
    __shared__ float As[BK][BM + 4];
    __shared__ float Bs[BK][BN];
    const int tid = threadIdx.x;
    const int m0 = blockIdx.y * BM;
    const int n0 = blockIdx.x * BN;
    const int tx = tid & 15;
    const int ty = tid >> 4;

    float acc[4][4];
#pragma unroll
    for (int i = 0; i < 4; ++i)
#pragma unroll
        for (int j = 0; j < 4; ++j) acc[i][j] = 0.f;

    for (int k0 = 0; k0 < NIN; k0 += BK) {
#pragma unroll
        for (int i = tid; i < BM * BK / 4; i += 256) {
            int m = i >> 2, kq = i & 3;
            float4 v = *(const float4*)(A + (long)(m0 + m) * NIN + k0 + kq * 4);
            As[kq * 4 + 0][m] = v.x;
            As[kq * 4 + 1][m] = v.y;
            As[kq * 4 + 2][m] = v.z;
            As[kq * 4 + 3][m] = v.w;
        }
#pragma unroll
        for (int i = tid; i < BK * BN / 4; i += 256) {
            int kk = i >> 4, nq = i & 15;
            *(float4*)(&Bs[kk][nq * 4]) =
                *(const float4*)(Bm + (long)(k0 + kk) * NH + n0 + nq * 4);
        }
        __syncthreads();

#pragma unroll
        for (int kk = 0; kk < BK; ++kk) {
            float4 a4 = *(const float4*)(&As[kk][ty * 4]);
            float4 b4 = *(const float4*)(&Bs[kk][tx * 4]);
            acc[0][0] = fmaf(a4.x, b4.x, acc[0][0]);
            acc[0][1] = fmaf(a4.x, b4.y, acc[0][1]);
            acc[0][2] = fmaf(a4.x, b4.z, acc[0][2]);
            acc[0][3] = fmaf(a4.x, b4.w, acc[0][3]);
            acc[1][0] = fmaf(a4.y, b4.x, acc[1][0]);
            acc[1][1] = fmaf(a4.y, b4.y, acc[1][1]);
            acc[1][2] = fmaf(a4.y, b4.z, acc[1][2]);
            acc[1][3] = fmaf(a4.y, b4.w, acc[1][3]);
            acc[2][0] = fmaf(a4.z, b4.x, acc[2][0]);
            acc[2][1] = fmaf(a4.z, b4.y, acc[2][1]);
            acc[2][2] = fmaf(a4.z, b4.z, acc[2][2]);
            acc[2][3] = fmaf(a4.z, b4.w, acc[2][3]);
            acc[3][0] = fmaf(a4.w, b4.x, acc[3][0]);
            acc[3][1] = fmaf(a4.w, b4.y, acc[3][1]);
            acc[3][2] = fmaf(a4.w, b4.z, acc[3][2]);
            acc[3][3] = fmaf(a4.w, b4.w, acc[3][3]);
        }
        __syncthreads();
    }

#pragma unroll
    for (int i = 0; i < 4; ++i) {
        const int m = m0 + ty * 4 + i;
#pragma unroll
        for (int j = 0; j < 4; ++j) {
            const int n = n0 + tx * 4 + j;
            C[(long)m * NH + n] = acc[i][j] + bias[n];
        }
    }
}

// ---------------- Phase B: persistent recurrent kernel (clustered) ----------
// 16 clusters (batch groups, 4 batches each) x 8 CTAs (64 hidden cols each).
// W slice [512k x 64c] lives in REGISTERS (c-pair packed u64, 128 regs/thr).
// fr exchanged via st.shared::cluster into peers' SMEM, double-buffered,
// synchronized by 2 cluster-scope mbarriers (count=8). Compute uses FFMA2.
// CRITICAL: no remote traffic is generated at t==NT, and a trailing cluster
// barrier guards exit (DSMEM writes to an exited CTA are UB -> R4 crash).

__global__ __launch_bounds__(NTHR, 1) __cluster_dims__(CLU, 1, 1)
void step_kernel(const float* __restrict__ W_hid,
                 const float* __restrict__ b_hid,
                 const float* __restrict__ alpha,
                 const float* __restrict__ init_state,
                 float* __restrict__ out) {
    __shared__ float    frs[2][NH * 4];     // [buf][k][b]  (k = hidden, b = 4 batches)
    __shared__ uint64_t red[8 * 132];       // 8 partials x [4b][32 cpairs] + pad
    __shared__ uint64_t bar[2];

    const int tid = threadIdx.x;
    uint32_t rank;
    asm("mov.u32 %0, %%cluster_ctarank;" : "=r"(rank));
    const int bb = blockIdx.x >> 3;         // batch group
    const int B0 = bb * 4;
    const int C0 = (int)rank * 64;

    const int kt = tid >> 4;                // 0..15 : K slice (32 k each)
    const int cg = tid & 15;                // 0..15 : c quad
    const int ktbase = kt * 32;

    const int eb = tid >> 6;                // 0..3  : output batch
    const int ec = tid & 63;                // 0..63 : output col
    const int gb = B0 + eb;
    const int gc = C0 + ec;

    // ---- W slice into registers, c-pair packed: w0={c0,c1}, w1={c2,c3} ----
    uint64_t w0[32], w1[32];
#pragma unroll
    for (int kk = 0; kk < 32; ++kk) {
        float4 w = *(const float4*)(W_hid + (long)(ktbase + kk) * NH + C0 + cg * 4);
        w0[kk] = pk2(w.x, w.y);
        w1[kk] = pk2(w.z, w.w);
    }

    // ---- mbarriers (count = 8: one arrive per cluster CTA per phase) ----
    const uint32_t bar0 = sm_u32(&bar[0]);
    const uint32_t bar1 = sm_u32(&bar[1]);
    if (tid == 0) {
        asm volatile("mbarrier.init.shared.b64 [%0], 8;" :: "r"(bar0) : "memory");
        asm volatile("mbarrier.init.shared.b64 [%0], 8;" :: "r"(bar1) : "memory");
    }

    // ---- buf0 = fr(0), computed locally (no exchange needed) ----
    for (int i = tid; i < NH * 4; i += NTHR) {
        int k = i >> 2, b = i & 3;
        frs[0][i] = fmaxf(init_state[(long)(B0 + b) * NH + k], 0.f);
    }

    float v = init_state[(long)gb * NH + gc];
    const float al  = alpha[gc];
    const float bh  = b_hid[gc];
    const float oma = 1.f - al;

    __syncthreads();
    // barriers + buf0 visible cluster-wide before any arrives/writes land
    asm volatile("barrier.cluster.arrive.aligned;" ::: "memory");
    asm volatile("barrier.cluster.wait.aligned;" ::: "memory");

    int ph0 = 0, ph1 = 0;
    for (int t = 1; t <= NT; ++t) {
        const long  oidx = ((long)gb * NT + (t - 1)) * NH + gc;
        const float vin  = out[oidx];                 // DRAM prefetch, hidden

        // wait for fr(t-1) in buf[(t-1)&1]  (t==1: local buf0, no wait)
        if (t >= 2) {
            if ((t - 1) & 1) { WAITC(bar1, ph1); ph1 ^= 1; }
            else             { WAITC(bar0, ph0); ph0 ^= 1; }
        }

        const float* fp = frs[(t - 1) & 1] + ktbase * 4;

        // ---- register-tiled FFMA2 GEMM over K slice ----
        uint64_t a00 = 0, a01 = 0, a10 = 0, a11 = 0,
                 a20 = 0, a21 = 0, a30 = 0, a31 = 0;
#pragma unroll
        for (int kk = 0; kk < 32; ++kk) {
            float4 f4 = *(const float4*)(fp + kk * 4);
            uint64_t fd0 = pk2(f4.x, f4.x);
            uint64_t fd1 = pk2(f4.y, f4.y);
            uint64_t fd2 = pk2(f4.z, f4.z);
            uint64_t fd3 = pk2(f4.w, f4.w);
            a00 = fma2(fd0, w0[kk], a00);  a01 = fma2(fd0, w1[kk], a01);
            a10 = fma2(fd1, w0[kk], a10);  a11 = fma2(fd1, w1[kk], a11);
            a20 = fma2(fd2, w0[kk], a20);  a21 = fma2(fd2, w1[kk], a21);
            a30 = fma2(fd3, w0[kk], a30);  a31 = fma2(fd3, w1[kk], a31);
        }

        // ---- pair-reduce kt with kt^1 (lane xor 16 within warp) ----
        a00 = add2(a00, __shfl_xor_sync(0xffffffffu, a00, 16));
        a01 = add2(a01, __shfl_xor_sync(0xffffffffu, a01, 16));
        a10 = add2(a10, __shfl_xor_sync(0xffffffffu, a10, 16));
        a11 = add2(a11, __shfl_xor_sync(0xffffffffu, a11, 16));
        a20 = add2(a20, __shfl_xor_sync(0xffffffffu, a20, 16));
        a21 = add2(a21, __shfl_xor_sync(0xffffffffu, a21, 16));
        a30 = add2(a30, __shfl_xor_sync(0xffffffffu, a30, 16));
        a31 = add2(a31, __shfl_xor_sync(0xffffffffu, a31, 16));

        if ((tid & 16) == 0) {             // kt even
            uint64_t* rp = red + (kt >> 1) * 132 + cg * 2;
            rp[0 * 32] = a00;  rp[0 * 32 + 1] = a01;
            rp[1 * 32] = a10;  rp[1 * 32 + 1] = a11;
            rp[2 * 32] = a20;  rp[2 * 32 + 1] = a21;
            rp[3 * 32] = a30;  rp[3 * 32 + 1] = a31;
        }
        __syncthreads();

        // ---- fold 8 partials + leaky update ----
        const float* rf = (const float*)red;
        float s = 0.f;
#pragma unroll
        for (int p = 0; p < 8; ++p)
            s += rf[p * 264 + eb * 64 + ec];

        v = oma * v + al * (s + bh + vin);
        const float fr = fmaxf(v, 0.f);
        out[oidx] = fr;

        // ---- scatter fr(t) to all peers + arrive — SKIP on last step ----
        if (t < NT) {
            const uint32_t laddr = sm_u32(&frs[t & 1][(C0 + ec) * 4 + eb]);
#pragma unroll
            for (int r = 0; r < CLU; ++r) {
                uint32_t ra;
                asm volatile("mapa.shared::cluster.u32 %0, %1, %2;"
                             : "=r"(ra) : "r"(laddr), "r"(r));
                asm volatile("st.shared::cluster.f32 [%0], %1;"
                             :: "r"(ra), "f"(fr) : "memory");
            }
            __syncthreads();                // all scatter stores issued
            if (tid == 0) {
                asm volatile("fence.acq_rel.cluster;" ::: "memory");
                const uint32_t lb = (t & 1) ? bar1 : bar0;
#pragma unroll
                for (int r = 0; r < CLU; ++r) ARRIVE_REMOTE(lb, r);
            }
        }
    }

    // guard exit: no CTA leaves while peers' DSMEM traffic could target it
    asm volatile("barrier.cluster.arrive.aligned;" ::: "memory");
    asm volatile("barrier.cluster.wait.aligned;" ::: "memory");
}

// ---------------- launch ----------------------------------------------------
extern "C" void kernel_launch(void* const* d_in, const int* in_sizes, int n_in,
                              void* d_out, int out_size) {
    const float* x     = (const float*)d_in[0];
    const float* init  = (const float*)d_in[1];
    const float* W_in  = (const float*)d_in[2];
    const float* b_in  = (const float*)d_in[3];
    const float* W_hid = (const float*)d_in[4];
    const float* b_hid = (const float*)d_in[5];
    const float* alpha = (const float*)d_in[6];
    float* out = (float*)d_out;

    dim3 grid(NH / BN, (NB * NT) / BM);   // (8, 1024)
    gemm_vin<<<grid, 256>>>(x, W_in, b_in, out);

    step_kernel<<<NCTA, NTHR>>>(W_hid, b_hid, alpha, init, out);
}

// round 6
// speedup vs baseline: 1.1914x; 1.1914x over previous
#include <cuda_runtime.h>
#include <cstdint>

#define NB   64
#define NT   1024
#define NIN  256
#define NH   512
#define NTHR 256
#define CLU  8                    // cluster size = col-blocks per batch group
#define NGRP 16                   // batch groups (independent clusters)
#define NCTA (NGRP * CLU)

#define WST  68                   // Wsm row stride (floats)
#define RBST 68                   // red per-batch stride
#define RPST 272                  // red per-partial stride (4*68)

// smem layout (floats)
#define OFF_W    0
#define OFF_FRS  (NH * WST)                 // 34816
#define OFF_RED  (OFF_FRS + 2 * NH * 4)     // 38912
#define OFF_BAR  (OFF_RED + 8 * RPST)       // 41088
#define SMEM_FLOATS (OFF_BAR + 4)
#define SMEM_BYTES  (SMEM_FLOATS * 4)

// ---------------- f32x2 packed helpers (sm_103a) -----------------------------
__device__ __forceinline__ uint64_t pk2(float x, float y) {
    uint64_t d; asm("mov.b64 %0, {%1, %2};" : "=l"(d) : "f"(x), "f"(y)); return d;
}
__device__ __forceinline__ uint64_t fma2(uint64_t a, uint64_t b, uint64_t c) {
    uint64_t d; asm("fma.rn.f32x2 %0, %1, %2, %3;" : "=l"(d) : "l"(a), "l"(b), "l"(c)); return d;
}
__device__ __forceinline__ uint64_t add2(uint64_t a, uint64_t b) {
    uint64_t d; asm("add.rn.f32x2 %0, %1, %2;" : "=l"(d) : "l"(a), "l"(b)); return d;
}
__device__ __forceinline__ uint64_t shflx16(uint64_t v) {
    return (uint64_t)__shfl_xor_sync(0xffffffffu, (unsigned long long)v, 16);
}
__device__ __forceinline__ uint32_t sm_u32(const void* p) {
    return (uint32_t)__cvta_generic_to_shared(p);
}

#define WAITC(addr, ph) do {                                                   \
    uint32_t _done;                                                            \
    do {                                                                       \
        asm volatile("{\n\t.reg .pred p;\n\t"                                  \
            "mbarrier.try_wait.parity.acquire.cluster.shared::cta.b64 p, [%1], %2, 0x989680;\n\t" \
            "selp.b32 %0, 1, 0, p;\n\t}"                                       \
            : "=r"(_done) : "r"(addr), "r"(ph) : "memory");                    \
    } while (!_done);                                                          \
} while (0)

#define ARRIVE_REMOTE(laddr, r) do {                                           \
    uint32_t _ra;                                                              \
    asm volatile("mapa.shared::cluster.u32 %0, %1, %2;"                        \
                 : "=r"(_ra) : "r"(laddr), "r"(r));                            \
    asm volatile("mbarrier.arrive.release.cluster.shared::cluster.b64 _, [%0];"\
                 :: "r"(_ra) : "memory");                                      \
} while (0)

// ---------------- Phase A: v_in = x @ W_in + b_in -> d_out -------------------
#define BM 64
#define BN 64
#define BK 16

__global__ __launch_bounds__(256) void gemm_vin(const float* __restrict__ A,
                                                const float* __restrict__ Bm,
                                                const float* __restrict__ bias,
                                                float* __restrict__ C) {
    __shared__ float As[BK][BM + 4];
    __shared__ float Bs[BK][BN];
    const int tid = threadIdx.x;
    const int m0 = blockIdx.y * BM;
    const int n0 = blockIdx.x * BN;
    const int tx = tid & 15;
    const int ty = tid >> 4;

    float acc[4][4];
#pragma unroll
    for (int i = 0; i < 4; ++i)
#pragma unroll
        for (int j = 0; j < 4; ++j) acc[i][j] = 0.f;

    for (int k0 = 0; k0 < NIN; k0 += BK) {
#pragma unroll
        for (int i = tid; i < BM * BK / 4; i += 256) {
            int m = i >> 2, kq = i & 3;
            float4 v = *(const float4*)(A + (long)(m0 + m) * NIN + k0 + kq * 4);
            As[kq * 4 + 0][m] = v.x;
            As[kq * 4 + 1][m] = v.y;
            As[kq * 4 + 2][m] = v.z;
            As[kq * 4 + 3][m] = v.w;
        }
#pragma unroll
        for (int i = tid; i < BK * BN / 4; i += 256) {
            int kk = i >> 4, nq = i & 15;
            *(float4*)(&Bs[kk][nq * 4]) =
                *(const float4*)(Bm + (long)(k0 + kk) * NH + n0 + nq * 4);
        }
        __syncthreads();

#pragma unroll
        for (int kk = 0; kk < BK; ++kk) {
            float4 a4 = *(const float4*)(&As[kk][ty * 4]);
            float4 b4 = *(const float4*)(&Bs[kk][tx * 4]);
            acc[0][0] = fmaf(a4.x, b4.x, acc[0][0]);
            acc[0][1] = fmaf(a4.x, b4.y, acc[0][1]);
            acc[0][2] = fmaf(a4.x, b4.z, acc[0][2]);
            acc[0][3] = fmaf(a4.x, b4.w, acc[0][3]);
            acc[1][0] = fmaf(a4.y, b4.x, acc[1][0]);
            acc[1][1] = fmaf(a4.y, b4.y, acc[1][1]);
            acc[1][2] = fmaf(a4.y, b4.z, acc[1][2]);
            acc[1][3] = fmaf(a4.y, b4.w, acc[1][3]);
            acc[2][0] = fmaf(a4.z, b4.x, acc[2][0]);
            acc[2][1] = fmaf(a4.z, b4.y, acc[2][1]);
            acc[2][2] = fmaf(a4.z, b4.z, acc[2][2]);
            acc[2][3] = fmaf(a4.z, b4.w, acc[2][3]);
            acc[3][0] = fmaf(a4.w, b4.x, acc[3][0]);
            acc[3][1] = fmaf(a4.w, b4.y, acc[3][1]);
            acc[3][2] = fmaf(a4.w, b4.z, acc[3][2]);
            acc[3][3] = fmaf(a4.w, b4.w, acc[3][3]);
        }
        __syncthreads();
    }

#pragma unroll
    for (int i = 0; i < 4; ++i) {
        const int m = m0 + ty * 4 + i;
#pragma unroll
        for (int j = 0; j < 4; ++j) {
            const int n = n0 + tx * 4 + j;
            C[(long)m * NH + n] = acc[i][j] + bias[n];
        }
    }
}

// ---------------- Phase B: persistent recurrent kernel (clustered) ----------
// 16 clusters (4 batches) x 8 CTAs (64 cols). W slice in SMEM (no spills),
// FFMA2 compute, fr exchanged via st.shared::cluster (float4, shfl-gathered),
// double-buffered, 2 cluster mbarriers. No remote traffic at t==NT; trailing
// cluster barrier guards exit.

__global__ __launch_bounds__(NTHR, 1) __cluster_dims__(CLU, 1, 1)
void step_kernel(const float* __restrict__ W_hid,
                 const float* __restrict__ b_hid,
                 const float* __restrict__ alpha,
                 const float* __restrict__ init_state,
                 float* __restrict__ out) {
    extern __shared__ float sh[];
    float*    Wsm  = sh + OFF_W;            // [512][68]
    float*    frs0 = sh + OFF_FRS;          // [512][4]
    float*    frs1 = sh + OFF_FRS + NH * 4; // [512][4]
    float*    redf = sh + OFF_RED;          // [8][4][68]
    uint64_t* bar  = (uint64_t*)(sh + OFF_BAR);

    const int tid = threadIdx.x;
    uint32_t rank;
    asm("mov.u32 %0, %%cluster_ctarank;" : "=r"(rank));
    const int bb = blockIdx.x >> 3;
    const int B0 = bb * 4;
    const int C0 = (int)rank * 64;

    const int kt = tid >> 4;                // 0..15 : K slice
    const int cg = tid & 15;                // 0..15 : c quad
    const int ktbase = kt * 32;

    const int eb = tid & 3;                 // 0..3  : output batch
    const int ec = tid >> 2;                // 0..63 : output col
    const int gb = B0 + eb;
    const int gc = C0 + ec;

    // ---- one-time W slice: Wsm[k][c] = W_hid[k][C0+c] ----
    for (int i = tid; i < NH * 16; i += NTHR) {
        int k = i >> 4, cq = i & 15;
        *(float4*)(Wsm + k * WST + cq * 4) =
            *(const float4*)(W_hid + (long)k * NH + C0 + cq * 4);
    }

    const uint32_t bar0 = sm_u32(&bar[0]);
    const uint32_t bar1 = sm_u32(&bar[1]);
    if (tid == 0) {
        asm volatile("mbarrier.init.shared.b64 [%0], 8;" :: "r"(bar0) : "memory");
        asm volatile("mbarrier.init.shared.b64 [%0], 8;" :: "r"(bar1) : "memory");
    }

    // ---- buf0 = fr(0), local ----
    for (int i = tid; i < NH * 4; i += NTHR) {
        int k = i >> 2, b = i & 3;
        frs0[i] = fmaxf(init_state[(long)(B0 + b) * NH + k], 0.f);
    }

    float v = init_state[(long)gb * NH + gc];
    const float al  = alpha[gc];
    const float bh  = b_hid[gc];
    const float oma = 1.f - al;

    __syncthreads();
    asm volatile("barrier.cluster.arrive.aligned;" ::: "memory");
    asm volatile("barrier.cluster.wait.aligned;" ::: "memory");

    const float* wp = Wsm + ktbase * WST + cg * 4;

    int ph0 = 0, ph1 = 0;
    for (int t = 1; t <= NT; ++t) {
        const long  oidx = ((long)gb * NT + (t - 1)) * NH + gc;
        const float vin  = out[oidx];                 // DRAM prefetch

        if (t >= 2) {
            if ((t - 1) & 1) { WAITC(bar1, ph1); ph1 ^= 1; }
            else             { WAITC(bar0, ph0); ph0 ^= 1; }
        }

        const float* fp = (((t - 1) & 1) ? frs1 : frs0) + ktbase * 4;

        // ---- FFMA2 GEMM over K slice: w quads from SMEM, f dup-packed ----
        uint64_t a00 = 0, a01 = 0, a10 = 0, a11 = 0,
                 a20 = 0, a21 = 0, a30 = 0, a31 = 0;
#pragma unroll 8
        for (int kk = 0; kk < 32; ++kk) {
            float4     f4 = *(const float4*)(fp + kk * 4);
            ulonglong2 wv = *(const ulonglong2*)(wp + kk * WST);
            uint64_t fd0 = pk2(f4.x, f4.x);
            uint64_t fd1 = pk2(f4.y, f4.y);
            uint64_t fd2 = pk2(f4.z, f4.z);
            uint64_t fd3 = pk2(f4.w, f4.w);
            a00 = fma2(fd0, wv.x, a00);  a01 = fma2(fd0, wv.y, a01);
            a10 = fma2(fd1, wv.x, a10);  a11 = fma2(fd1, wv.y, a11);
            a20 = fma2(fd2, wv.x, a20);  a21 = fma2(fd2, wv.y, a21);
            a30 = fma2(fd3, wv.x, a30);  a31 = fma2(fd3, wv.y, a31);
        }

        // ---- pair-reduce kt with kt^1 ----
        a00 = add2(a00, shflx16(a00));  a01 = add2(a01, shflx16(a01));
        a10 = add2(a10, shflx16(a10));  a11 = add2(a11, shflx16(a11));
        a20 = add2(a20, shflx16(a20));  a21 = add2(a21, shflx16(a21));
        a30 = add2(a30, shflx16(a30));  a31 = add2(a31, shflx16(a31));

        if ((tid & 16) == 0) {             // kt even -> partial p = kt>>1
            float* rp = redf + (kt >> 1) * RPST + cg * 4;
            *(uint64_t*)(rp + 0 * RBST)     = a00;
            *(uint64_t*)(rp + 0 * RBST + 2) = a01;
            *(uint64_t*)(rp + 1 * RBST)     = a10;
            *(uint64_t*)(rp + 1 * RBST + 2) = a11;
            *(uint64_t*)(rp + 2 * RBST)     = a20;
            *(uint64_t*)(rp + 2 * RBST + 2) = a21;
            *(uint64_t*)(rp + 3 * RBST)     = a30;
            *(uint64_t*)(rp + 3 * RBST + 2) = a31;
        }
        __syncthreads();

        // ---- fold 8 partials + leaky update (thread owns (eb,ec)) ----
        float s = 0.f;
#pragma unroll
        for (int p = 0; p < 8; ++p)
            s += redf[p * RPST + eb * RBST + ec];

        v = oma * v + al * (s + bh + vin);
        const float fr = fmaxf(v, 0.f);
        out[oidx] = fr;

        // ---- scatter fr(t): gather b-quad via shfl, ST.128 to 8 peers ----
        if (t < NT) {
            const float g0 = __shfl_sync(0xffffffffu, fr, 0, 4);
            const float g1 = __shfl_sync(0xffffffffu, fr, 1, 4);
            const float g2 = __shfl_sync(0xffffffffu, fr, 2, 4);
            const float g3 = __shfl_sync(0xffffffffu, fr, 3, 4);
            if (eb == 0) {
                float* dstbuf = (t & 1) ? frs1 : frs0;
                const uint32_t laddr = sm_u32(dstbuf + gc * 4);
#pragma unroll
                for (int r = 0; r < CLU; ++r) {
                    uint32_t ra;
                    asm volatile("mapa.shared::cluster.u32 %0, %1, %2;"
                                 : "=r"(ra) : "r"(laddr), "r"(r));
                    asm volatile("st.shared::cluster.v4.f32 [%0], {%1, %2, %3, %4};"
                                 :: "r"(ra), "f"(g0), "f"(g1), "f"(g2), "f"(g3)
                                 : "memory");
                }
            }
            __syncthreads();
            if (tid == 0) {
                asm volatile("fence.acq_rel.cluster;" ::: "memory");
                const uint32_t lb = (t & 1) ? bar1 : bar0;
#pragma unroll
                for (int r = 0; r < CLU; ++r) ARRIVE_REMOTE(lb, r);
            }
        }
    }

    asm volatile("barrier.cluster.arrive.aligned;" ::: "memory");
    asm volatile("barrier.cluster.wait.aligned;" ::: "memory");
}

// ---------------- launch ----------------------------------------------------
extern "C" void kernel_launch(void* const* d_in, const int* in_sizes, int n_in,
                              void* d_out, int out_size) {
    const float* x     = (const float*)d_in[0];
    const float* init  = (const float*)d_in[1];
    const float* W_in  = (const float*)d_in[2];
    const float* b_in  = (const float*)d_in[3];
    const float* W_hid = (const float*)d_in[4];
    const float* b_hid = (const float*)d_in[5];
    const float* alpha = (const float*)d_in[6];
    float* out = (float*)d_out;

    cudaFuncSetAttribute(step_kernel,
                         cudaFuncAttributeMaxDynamicSharedMemorySize, SMEM_BYTES);

    dim3 grid(NH / BN, (NB * NT) / BM);   // (8, 1024)
    gemm_vin<<<grid, 256>>>(x, W_in, b_in, out);

    step_kernel<<<NCTA, NTHR, SMEM_BYTES>>>(W_hid, b_hid, alpha, init, out);
}

// round 7
// speedup vs baseline: 1.8553x; 1.5573x over previous
#include <cuda_runtime.h>
#include <cstdint>

#define NB   64
#define NT   1024
#define NIN  256
#define NH   512
#define NTHB 512     // step kernel threads
#define NCTA 128     // 4 batch-groups x 32 col-groups
#define GSZ  32      // CTAs per barrier group

#define RB 20        // red per-col stride (floats)
#define RC 320       // red per-kt stride (16*RB)

// smem floats: wd 16384 (64KB u64 view) + frs 8192 + red 5120
#define SM_FRS 16384
#define SM_RED (16384 + 8192)
#define SMEM_FLOATS (SM_RED + 16 * RC)
#define SMEM_BYTES (SMEM_FLOATS * 4)

// ---------------- device globals (scratch; no allocations allowed) ----------
__device__ unsigned g_bars[4 * 32];          // per-bgrp counters, 128B apart
__device__ float    g_fr[2][NH * NB];        // [hid][batch], double buffered

__global__ void init_kernel() {
    if (threadIdx.x < 4) g_bars[threadIdx.x * 32] = 0u;
}

// ---------------- f32x2 helpers (sm_103a) ------------------------------------
__device__ __forceinline__ uint64_t pk2(float x, float y) {
    uint64_t d; asm("mov.b64 %0, {%1, %2};" : "=l"(d) : "f"(x), "f"(y)); return d;
}
__device__ __forceinline__ uint64_t fma2(uint64_t a, uint64_t b, uint64_t c) {
    uint64_t d; asm("fma.rn.f32x2 %0, %1, %2, %3;" : "=l"(d) : "l"(a), "l"(b), "l"(c)); return d;
}

// ---------------- Phase A: v_in = x @ W_in + b_in -> d_out -------------------
#define BM 64
#define BN 64
#define BK 16

__global__ __launch_bounds__(256) void gemm_vin(const float* __restrict__ A,
                                                const float* __restrict__ Bm,
                                                const float* __restrict__ bias,
                                                float* __restrict__ C) {
    __shared__ float As[BK][BM + 4];
    __shared__ float Bs[BK][BN];
    const int tid = threadIdx.x;
    const int m0 = blockIdx.y * BM;
    const int n0 = blockIdx.x * BN;
    const int tx = tid & 15;
    const int ty = tid >> 4;

    float acc[4][4];
#pragma unroll
    for (int i = 0; i < 4; ++i)
#pragma unroll
        for (int j = 0; j < 4; ++j) acc[i][j] = 0.f;

    for (int k0 = 0; k0 < NIN; k0 += BK) {
#pragma unroll
        for (int i = tid; i < BM * BK / 4; i += 256) {
            int m = i >> 2, kq = i & 3;
            float4 v = *(const float4*)(A + (long)(m0 + m) * NIN + k0 + kq * 4);
            As[kq * 4 + 0][m] = v.x;
            As[kq * 4 + 1][m] = v.y;
            As[kq * 4 + 2][m] = v.z;
            As[kq * 4 + 3][m] = v.w;
        }
#pragma unroll
        for (int i = tid; i < BK * BN / 4; i += 256) {
            int kk = i >> 4, nq = i & 15;
            *(float4*)(&Bs[kk][nq * 4]) =
                *(const float4*)(Bm + (long)(k0 + kk) * NH + n0 + nq * 4);
        }
        __syncthreads();

#pragma unroll
        for (int kk = 0; kk < BK; ++kk) {
            float4 a4 = *(const float4*)(&As[kk][ty * 4]);
            float4 b4 = *(const float4*)(&Bs[kk][tx * 4]);
            acc[0][0] = fmaf(a4.x, b4.x, acc[0][0]);
            acc[0][1] = fmaf(a4.x, b4.y, acc[0][1]);
            acc[0][2] = fmaf(a4.x, b4.z, acc[0][2]);
            acc[0][3] = fmaf(a4.x, b4.w, acc[0][3]);
            acc[1][0] = fmaf(a4.y, b4.x, acc[1][0]);
            acc[1][1] = fmaf(a4.y, b4.y, acc[1][1]);
            acc[1][2] = fmaf(a4.y, b4.z, acc[1][2]);
            acc[1][3] = fmaf(a4.y, b4.w, acc[1][3]);
            acc[2][0] = fmaf(a4.z, b4.x, acc[2][0]);
            acc[2][1] = fmaf(a4.z, b4.y, acc[2][1]);
            acc[2][2] = fmaf(a4.z, b4.z, acc[2][2]);
            acc[2][3] = fmaf(a4.z, b4.w, acc[2][3]);
            acc[3][0] = fmaf(a4.w, b4.x, acc[3][0]);
            acc[3][1] = fmaf(a4.w, b4.y, acc[3][1]);
            acc[3][2] = fmaf(a4.w, b4.z, acc[3][2]);
            acc[3][3] = fmaf(a4.w, b4.w, acc[3][3]);
        }
        __syncthreads();
    }

#pragma unroll
    for (int i = 0; i < 4; ++i) {
        const int m = m0 + ty * 4 + i;
#pragma unroll
        for (int j = 0; j < 4; ++j) {
            const int n = n0 + tx * 4 + j;
            C[(long)m * NH + n] = acc[i][j] + bias[n];
        }
    }
}

// ---------------- Phase B: persistent recurrent kernel ----------------------
// 128 CTAs = 4 batch-groups (16 batches) x 32 col-groups (16 cols), 512 thr.
// W as pre-duplicated f32x2 pairs in SMEM: warp-kk W read = 128B = 1 wavefront.
// Inner loop: 2x LDS.128 + 4x FFMA2 per kk, no pack MOVs.
// Exchange through L2 (stcg/ldcg) with per-group monotonic atomic barrier.

__global__ __launch_bounds__(NTHB, 1) void step_kernel(
    const float* __restrict__ W_hid,
    const float* __restrict__ b_hid,
    const float* __restrict__ alpha,
    const float* __restrict__ init_state,
    float* __restrict__ out) {
    extern __shared__ float sh[];
    uint64_t* wd  = (uint64_t*)sh;        // [512][16] u64, wd[k*16+c] = {w,w}
    float*    frs = sh + SM_FRS;          // [512][16]  (k-major, 16 batches)
    float*    red = sh + SM_RED;          // [16 kt][16 c][RB]

    const int tid  = threadIdx.x;
    const int bgrp = blockIdx.x >> 5;     // 0..3
    const int cgrp = blockIdx.x & 31;     // 0..31
    const int B0   = bgrp * 16;
    const int C0   = cgrp * 16;
    unsigned* bar  = &g_bars[bgrp * 32];

    // compute roles: warp = kt, lanes = (bg, cg)
    const int kt = tid >> 5;              // 0..15 (32 k each)
    const int bg = (tid >> 3) & 3;        // 0..3  (4 batches)
    const int cg = tid & 7;               // 0..7  (2 cols)
    // fold roles (tid < 256)
    const int ec = tid & 15;
    const int eb = (tid >> 4) & 15;
    const int gb = B0 + eb;
    const int gc = C0 + ec;

    // ---- one-time: W slice as duplicated pairs ----
    for (int i = tid; i < NH * 16; i += NTHB) {
        int k = i >> 4, c = i & 15;
        float w = W_hid[(long)k * NH + C0 + c];
        wd[i] = pk2(w, w);
    }

    // ---- init state; fr(0) into g_fr[0] ----
    float v = 0.f, al = 0.f, bh = 0.f, oma = 0.f;
    if (tid < 256) {
        v   = init_state[(long)gb * NH + gc];
        al  = alpha[gc];
        bh  = b_hid[gc];
        oma = 1.f - al;
        __stcg(&g_fr[0][gc * NB + gb], fmaxf(v, 0.f));
    }
    __syncthreads();

    unsigned epoch = 1;
    if (tid == 0) {
        __threadfence();
        atomicAdd(bar, 1u);
        while (*(volatile unsigned*)bar < epoch * GSZ) { }
        __threadfence();
    }
    __syncthreads();

    const float*    fp0 = frs + (kt * 32) * 16 + bg * 4;
    const uint64_t* wp0 = wd  + (kt * 32) * 16 + cg * 2;

    for (int t = 1; t <= NT; ++t) {
        long  oidx = 0;
        float vin  = 0.f;
        if (tid < 256) {
            oidx = ((long)gb * NT + (t - 1)) * NH + gc;
            vin  = out[oidx];                          // DRAM prefetch
        }

        // ---- stage fr(t-1): straight float4 copy, 4 per thread ----
        {
            const float* src = g_fr[(t - 1) & 1] + B0;
#pragma unroll
            for (int j = 0; j < 4; ++j) {
                int i = tid + j * NTHB;
                int k = i >> 2, q = i & 3;
                float4 vv = __ldcg((const float4*)(src + (long)k * NB) + q);
                *(float4*)(frs + k * 16 + q * 4) = vv;
            }
        }
        __syncthreads();

        // ---- inner GEMM: 32 kk x (2 LDS.128 + 4 FFMA2) ----
        uint64_t a00 = 0, a10 = 0, a01 = 0, a11 = 0;
#pragma unroll
        for (int kk = 0; kk < 32; ++kk) {
            ulonglong2 fv = *(const ulonglong2*)(fp0 + kk * 16);   // {b0,b1},{b2,b3}
            ulonglong2 wv = *(const ulonglong2*)(wp0 + kk * 16);   // {c0,c0},{c1,c1}
            a00 = fma2(fv.x, wv.x, a00);
            a10 = fma2(fv.y, wv.x, a10);
            a01 = fma2(fv.x, wv.y, a01);
            a11 = fma2(fv.y, wv.y, a11);
        }

        // ---- publish kt-partials ----
        {
            float* rp = red + kt * RC + (cg * 2) * RB + bg * 4;
            ulonglong2 s0; s0.x = a00; s0.y = a10;     // {b0..b3} col c0
            ulonglong2 s1; s1.x = a01; s1.y = a11;     // {b0..b3} col c1
            *(ulonglong2*)rp        = s0;
            *(ulonglong2*)(rp + RB) = s1;
        }
        __syncthreads();

        // ---- fold 16 partials + leaky update (thread owns (eb,ec)) ----
        if (tid < 256) {
            const float* rr = red + ec * RB + eb;
            float s0 = rr[0 * RC]  + rr[1 * RC];
            float s1 = rr[2 * RC]  + rr[3 * RC];
            float s2 = rr[4 * RC]  + rr[5 * RC];
            float s3 = rr[6 * RC]  + rr[7 * RC];
            float s4 = rr[8 * RC]  + rr[9 * RC];
            float s5 = rr[10 * RC] + rr[11 * RC];
            float s6 = rr[12 * RC] + rr[13 * RC];
            float s7 = rr[14 * RC] + rr[15 * RC];
            float s  = ((s0 + s1) + (s2 + s3)) + ((s4 + s5) + (s6 + s7));

            v = oma * v + al * (s + bh + vin);
            const float fr = fmaxf(v, 0.f);
            __stcg(&g_fr[t & 1][gc * NB + gb], fr);
            out[oidx] = fr;
        }
        __syncthreads();

        // ---- group barrier (skip after last step) ----
        if (t < NT) {
            ++epoch;
            if (tid == 0) {
                __threadfence();
                atomicAdd(bar, 1u);
                while (*(volatile unsigned*)bar < epoch * GSZ) { }
                __threadfence();
            }
            __syncthreads();
        }
    }
}

// ---------------- launch ----------------------------------------------------
extern "C" void kernel_launch(void* const* d_in, const int* in_sizes, int n_in,
                              void* d_out, int out_size) {
    const float* x     = (const float*)d_in[0];
    const float* init  = (const float*)d_in[1];
    const float* W_in  = (const float*)d_in[2];
    const float* b_in  = (const float*)d_in[3];
    const float* W_hid = (const float*)d_in[4];
    const float* b_hid = (const float*)d_in[5];
    const float* alpha = (const float*)d_in[6];
    float* out = (float*)d_out;

    cudaFuncSetAttribute(step_kernel,
                         cudaFuncAttributeMaxDynamicSharedMemorySize, SMEM_BYTES);

    init_kernel<<<1, 4>>>();

    dim3 grid(NH / BN, (NB * NT) / BM);   // (8, 1024)
    gemm_vin<<<grid, 256>>>(x, W_in, b_in, out);

    step_kernel<<<NCTA, NTHB, SMEM_BYTES>>>(W_hid, b_hid, alpha, init, out);
}